// round 3
// baseline (speedup 1.0000x reference)
#include <cuda_runtime.h>
#include <cstdint>

#define N_PTS 16384
#define M_PTS 4096
#define KNN_K 16
#define EMB   64
#define NEDGE (N_PTS*KNN_K)   // 262144
#define FLT_MAX_C 3.402823466e+38f

// ---------------- device scratch (static globals: allocation-free) ----------
__device__ int      g_idx[M_PTS];
__device__ float4   g_ps[M_PTS];          // sampled pos: x,y,z, sumsq
__device__ float    g_xs[M_PTS*EMB];      // gathered features
__device__ float    g_delta[M_PTS*3];     // h-MLP output per sampled point
__device__ float    g_u[N_PTS*EMB];       // x @ f_w1[3:,:] + f_b1  (pre-ReLU)
__device__ float    g_sn[N_PTS];          // ||pos||^2 per point
__device__ int      g_nbr[NEDGE];         // knn neighbor ids
__device__ float    g_hidden[NEDGE*EMB];  // per-edge layer-1 post-ReLU
__device__ unsigned g_aggr[M_PTS*EMB];    // encoded float max accumulators

// order-preserving float<->uint encoding for atomicMax
__device__ __forceinline__ unsigned encf(float f) {
    unsigned u = __float_as_uint(f);
    return (u & 0x80000000u) ? ~u : (u | 0x80000000u);
}
__device__ __forceinline__ float decf(unsigned u) {
    return (u & 0x80000000u) ? __uint_as_float(u & 0x7FFFFFFFu) : __uint_as_float(~u);
}

// ---------------- ||pos||^2 (matches jnp.sum(pos**2, axis=1) fp32 order) ----
__global__ void sn_kernel(const float* __restrict__ pos) {
    int i = blockIdx.x * 256 + threadIdx.x;
    if (i < N_PTS) {
        float x = pos[3*i], y = pos[3*i+1], z = pos[3*i+2];
        g_sn[i] = __fadd_rn(__fadd_rn(__fmul_rn(x,x), __fmul_rn(y,y)), __fmul_rn(z,z));
    }
}

// ---------------- FPS: single CTA, pos in smem, min_d in registers ----------
__global__ __launch_bounds__(1024, 1)
void fps_kernel(const float* __restrict__ pos) {
    extern __shared__ float sm[];
    float* px = sm;
    float* py = sm + N_PTS;
    float* pz = sm + 2*N_PTS;
    float* red = sm + 3*N_PTS;        // [0..31] warp maxes, [32] vmax
    int*   win = (int*)(red + 36);

    int t = threadIdx.x;
    for (int i = t; i < N_PTS; i += 1024) {
        px[i] = pos[3*i]; py[i] = pos[3*i+1]; pz[i] = pos[3*i+2];
    }
    float md[16];
#pragma unroll
    for (int j = 0; j < 16; j++) md[j] = FLT_MAX_C;

    if (t == 0) { g_idx[0] = 0; *win = 0x7FFFFFFF; }
    __syncthreads();

    float lx = px[0], ly = py[0], lz = pz[0];

    for (int it = 1; it < M_PTS; ++it) {
        float best = -1.0f;
#pragma unroll
        for (int j = 0; j < 16; j++) {
            int i = t + (j << 10);
            float dx = __fsub_rn(px[i], lx);
            float dy = __fsub_rn(py[i], ly);
            float dz = __fsub_rn(pz[i], lz);
            // ((dx^2 + dy^2) + dz^2) exactly as jnp (no fma contraction)
            float d = __fadd_rn(__fadd_rn(__fmul_rn(dx,dx), __fmul_rn(dy,dy)), __fmul_rn(dz,dz));
            md[j] = fminf(md[j], d);
            best  = fmaxf(best, md[j]);
        }
        // warp max
        for (int o = 16; o; o >>= 1) best = fmaxf(best, __shfl_xor_sync(0xFFFFFFFFu, best, o));
        if ((t & 31) == 0) red[t >> 5] = best;
        __syncthreads();
        if (t < 32) {
            float b = red[t];
            for (int o = 16; o; o >>= 1) b = fmaxf(b, __shfl_xor_sync(0xFFFFFFFFu, b, o));
            if (t == 0) red[32] = b;
        }
        __syncthreads();
        float vmax = red[32];
        // first index achieving vmax (jnp.argmax tie rule)
        int mybest = 0x7FFFFFFF;
#pragma unroll
        for (int j = 0; j < 16; j++) {
            int i = t + (j << 10);
            if (md[j] == vmax) mybest = min(mybest, i);
        }
        if (mybest != 0x7FFFFFFF) atomicMin_block(win, mybest);
        __syncthreads();
        int w = *win;
        lx = px[w]; ly = py[w]; lz = pz[w];
        if (t == 0) g_idx[it] = w;
        __syncthreads();
        if (t == 0) *win = 0x7FFFFFFF;   // safe: next atomicMin is 2 barriers away
    }
}

// ---------------- gather: x_s, pos_s (+sumsq), write pos_s to output --------
__global__ void gather_kernel(const float* __restrict__ pos, const float* __restrict__ x,
                              float* __restrict__ out) {
    int gid = blockIdx.x * 256 + threadIdx.x;   // 0 .. M*64-1
    int m = gid >> 6, c = gid & 63;
    int i = g_idx[m];
    g_xs[gid] = x[i*64 + c];
    if (c == 0) {
        float a = pos[3*i], b = pos[3*i+1], d = pos[3*i+2];
        float s = __fadd_rn(__fadd_rn(__fmul_rn(a,a), __fmul_rn(b,b)), __fmul_rn(d,d));
        g_ps[m] = make_float4(a, b, d, s);
        out[262144 + m*3 + 0] = a;
        out[262144 + m*3 + 1] = b;
        out[262144 + m*3 + 2] = d;
    }
}

// ---------------- h-MLP on sampled points: delta = h(x_s)  [M,3] ------------
__global__ void h_kernel(const float* __restrict__ w1, const float* __restrict__ b1,
                         const float* __restrict__ w2, const float* __restrict__ b2) {
    __shared__ float xr[64];
    __shared__ float hid[64];
    int m = blockIdx.x, c = threadIdx.x;
    xr[c] = g_xs[m*64 + c];
    __syncthreads();
    float h = b1[c];
#pragma unroll 8
    for (int k = 0; k < 64; k++) h = fmaf(xr[k], w1[k*64 + c], h);
    hid[c] = fmaxf(h, 0.0f);
    __syncthreads();
    if (c < 3) {
        float o = b2[c];
#pragma unroll 8
        for (int k = 0; k < 64; k++) o = fmaf(hid[k], w2[k*3 + c], o);
        g_delta[m*3 + c] = o;
    }
}

// ---------------- u = x @ f_w1[3:,:] + f_b1   [N,64] (pre-ReLU) -------------
__global__ void u_kernel(const float* __restrict__ x, const float* __restrict__ fw1,
                         const float* __restrict__ fb1) {
    __shared__ float xr[64];
    int n = blockIdx.x, c = threadIdx.x;
    xr[c] = x[n*64 + c];
    __syncthreads();
    float h = fb1[c];
#pragma unroll 8
    for (int k = 0; k < 64; k++) h = fmaf(xr[k], fw1[(3 + k)*64 + c], h);
    g_u[n*64 + c] = h;
}

// ---------------- KNN: per query scan 4096, stable top-16 -------------------
// d2 replicates XLA bit-for-bit: dot is an ascending-k FMA chain (GEMM
// accumulation order), outer expression is (s_n + s_m) - 2*dot.
__global__ void knn_kernel(const float* __restrict__ pos, float* __restrict__ out) {
    extern __shared__ float4 sp[];
    int tid = threadIdx.x;
    for (int i = tid; i < M_PTS; i += 128) sp[i] = g_ps[i];
    __syncthreads();
    int n = blockIdx.x * 128 + tid;
    float qx = pos[3*n], qy = pos[3*n+1], qz = pos[3*n+2];
    float s_n = g_sn[n];
    float bd[KNN_K]; int bi[KNN_K];
#pragma unroll
    for (int j = 0; j < KNN_K; j++) { bd[j] = FLT_MAX_C; bi[j] = 0x7FFFFFFF; }
    float worst = FLT_MAX_C;
    for (int m = 0; m < M_PTS; m++) {
        float4 q = sp[m];
        // GEMM-order dot: acc = fma(qx,sx,0); acc = fma(qy,sy,acc); acc = fma(qz,sz,acc)
        float dot = __fmaf_rn(qz, q.z, __fmaf_rn(qy, q.y, __fmul_rn(qx, q.x)));
        float d2 = __fsub_rn(__fadd_rn(s_n, q.w), __fmul_rn(2.0f, dot));
        if (d2 < worst) {                   // strict: equal d2 -> earlier index kept
            float v = d2; int id = m;
#pragma unroll
            for (int j = 0; j < KNN_K; j++) {
                if (v < bd[j]) {
                    float tv = bd[j]; bd[j] = v;  v = tv;
                    int   ti = bi[j]; bi[j] = id; id = ti;
                }
            }
            worst = bd[KNN_K-1];
        }
    }
    float* osrc = out + 274432;
    float* otgt = out + 536576;
#pragma unroll
    for (int j = 0; j < KNN_K; j++) {
        g_nbr[n*KNN_K + j] = bi[j];
        osrc[n*KNN_K + j] = (float)n;
        otgt[n*KNN_K + j] = (float)bi[j];
    }
}

// ---------------- zero the aggregation buffer -------------------------------
__global__ void zero_aggr_kernel() {
    g_aggr[blockIdx.x * 256 + threadIdx.x] = 0u;
}

// ---------------- per-edge layer-1: hidden = relu(u[src] + a @ W3) ----------
__global__ void hidden_kernel(const float* __restrict__ pos, const float* __restrict__ fw1) {
    __shared__ float w3[192];
    __shared__ float av[4][3];
    int tid = threadIdx.x;                 // 256
    if (tid < 192) w3[tid] = fw1[tid];     // rows 0..2 of f_w1
    int gid = blockIdx.x * 256 + tid;
    int e = gid >> 6, c = gid & 63;
    int eg = tid >> 6;
    int n = e >> 4;
    int m = g_nbr[e];
    if (c < 3) {
        float pcomp = pos[3*n + c];
        float qcomp = ((const float*)&g_ps[m])[c];
        av[eg][c] = __fadd_rn(__fsub_rn(pcomp, qcomp), g_delta[m*3 + c]);
    }
    __syncthreads();
    float h = g_u[n*64 + c];
    h = fmaf(av[eg][0], w3[c],       h);
    h = fmaf(av[eg][1], w3[64 + c],  h);
    h = fmaf(av[eg][2], w3[128 + c], h);
    g_hidden[gid] = fmaxf(h, 0.0f);
}

// ---------------- per-edge layer-2 GEMM + atomicMax aggregation -------------
// tile: 32 edges x 64 outputs per block (128 threads; thread = 4 edges x 4 d)
__global__ __launch_bounds__(128)
void msg_kernel(const float* __restrict__ fw2, const float* __restrict__ fb2) {
    __shared__ float w2s[64*64];
    __shared__ float ht[32*65];           // padded to kill bank conflicts
    __shared__ int   tg[32];
    int tid = threadIdx.x;
    for (int i = tid; i < 4096; i += 128) w2s[i] = fw2[i];
    int e0 = blockIdx.x * 32;
    for (int i = tid; i < 2048; i += 128) {
        ht[(i >> 6)*65 + (i & 63)] = g_hidden[e0*64 + i];
    }
    if (tid < 32) tg[tid] = g_nbr[e0 + tid];
    __syncthreads();

    int te = (tid >> 4) * 4;              // edge base within tile
    int td = (tid & 15) * 4;              // output-dim base
    float acc[4][4];
    float b0 = fb2[td], b1 = fb2[td+1], b2v = fb2[td+2], b3 = fb2[td+3];
#pragma unroll
    for (int i = 0; i < 4; i++) { acc[i][0]=b0; acc[i][1]=b1; acc[i][2]=b2v; acc[i][3]=b3; }

#pragma unroll 4
    for (int k = 0; k < 64; k++) {
        float4 w = *(const float4*)&w2s[k*64 + td];
#pragma unroll
        for (int i = 0; i < 4; i++) {
            float hv = ht[(te + i)*65 + k];
            acc[i][0] = fmaf(hv, w.x, acc[i][0]);
            acc[i][1] = fmaf(hv, w.y, acc[i][1]);
            acc[i][2] = fmaf(hv, w.z, acc[i][2]);
            acc[i][3] = fmaf(hv, w.w, acc[i][3]);
        }
    }
#pragma unroll
    for (int i = 0; i < 4; i++) {
        unsigned* base = &g_aggr[tg[te + i]*64 + td];
        atomicMax(base + 0, encf(acc[i][0]));
        atomicMax(base + 1, encf(acc[i][1]));
        atomicMax(base + 2, encf(acc[i][2]));
        atomicMax(base + 3, encf(acc[i][3]));
    }
}

// ---------------- g-MLP + residual -> x_new (written as f32) ----------------
__global__ void out_kernel(const float* __restrict__ w1, const float* __restrict__ b1,
                           const float* __restrict__ w2, const float* __restrict__ b2,
                           float* __restrict__ out) {
    __shared__ float in[128];
    __shared__ float hid[64];
    int m = blockIdx.x, c = threadIdx.x;
    float xs = g_xs[m*64 + c];
    in[c] = xs;
    unsigned u = g_aggr[m*64 + c];
    in[64 + c] = (u == 0u) ? 0.0f : decf(u);   // isfinite-else-0 rule
    __syncthreads();
    float h = b1[c];
#pragma unroll 8
    for (int k = 0; k < 128; k++) h = fmaf(in[k], w1[k*64 + c], h);
    hid[c] = fmaxf(h, 0.0f);
    __syncthreads();
    float o = b2[c];
#pragma unroll 8
    for (int k = 0; k < 64; k++) o = fmaf(hid[k], w2[k*64 + c], o);
    out[m*64 + c] = xs + o;
}

// ---------------- launcher --------------------------------------------------
extern "C" void kernel_launch(void* const* d_in, const int* in_sizes, int n_in,
                              void* d_out, int out_size) {
    const float* x    = (const float*)d_in[0];
    const float* pos  = (const float*)d_in[1];
    // d_in[2] = edge_index (int64) -- unused by the reference math
    const float* h_w1 = (const float*)d_in[3];
    const float* h_b1 = (const float*)d_in[4];
    const float* h_w2 = (const float*)d_in[5];
    const float* h_b2 = (const float*)d_in[6];
    const float* f_w1 = (const float*)d_in[7];
    const float* f_b1 = (const float*)d_in[8];
    const float* f_w2 = (const float*)d_in[9];
    const float* f_b2 = (const float*)d_in[10];
    const float* g_w1 = (const float*)d_in[11];
    const float* g_b1 = (const float*)d_in[12];
    const float* g_w2 = (const float*)d_in[13];
    const float* g_b2 = (const float*)d_in[14];
    float* out = (float*)d_out;

    size_t fps_smem = (size_t)(3*N_PTS + 40) * sizeof(float);   // ~196.8 KB
    cudaFuncSetAttribute(fps_kernel, cudaFuncAttributeMaxDynamicSharedMemorySize, (int)fps_smem);
    cudaFuncSetAttribute(knn_kernel, cudaFuncAttributeMaxDynamicSharedMemorySize, M_PTS*16);

    sn_kernel<<<(N_PTS + 255)/256, 256>>>(pos);
    fps_kernel<<<1, 1024, fps_smem>>>(pos);
    gather_kernel<<<(M_PTS*EMB)/256, 256>>>(pos, x, out);
    h_kernel<<<M_PTS, 64>>>(h_w1, h_b1, h_w2, h_b2);
    u_kernel<<<N_PTS, 64>>>(x, f_w1, f_b1);
    zero_aggr_kernel<<<(M_PTS*EMB)/256, 256>>>();
    knn_kernel<<<N_PTS/128, 128, M_PTS*16>>>(pos, out);
    hidden_kernel<<<(NEDGE*EMB)/256, 256>>>(pos, f_w1);
    msg_kernel<<<NEDGE/32, 128>>>(f_w2, f_b2);
    out_kernel<<<M_PTS, 64>>>(g_w1, g_b1, g_w2, g_b2, out);
}